// round 17
// baseline (speedup 1.0000x reference)
#include <cuda_runtime.h>
#include <cuda_bf16.h>
#include <cuda_fp16.h>
#include <math.h>
#include <stdint.h>

// Problem dims
#define B_  512
#define H_  1024
#define L_  256
#define V_  10000
#define H2_ 2048
#define H3_ 3072

#define ATTN_S 16   // attn split-K factor
#define COMB_S 4    // comb split-K factor

// ---------------- scratch (device globals; no allocation) ----------------
__device__ float g_app[B_ * H_];        // attn_applied
__device__ float g_x[B_ * H_];
__device__ float g_gi[B_ * H3_];
__device__ float g_gh[B_ * H3_];
__device__ float g_part[ATTN_S * B_ * L_];  // 8MB; also holds COMB_S*B*H

// fp16 weight / activation mirrors
__device__ __half g_w_attn16[H2_ * L_];
__device__ __half g_w_comb16[H2_ * H_];
__device__ __half g_w_ih16[H_ * H3_];
__device__ __half g_w_hh16[H_ * H3_];
__device__ __half g_w_out16[H_ * V_];
__device__ __half g_hid16[B_ * H_];
__device__ __half g_x16[B_ * H_];
__device__ __half g_nh16[B_ * H_];

// ---------------- helpers ----------------
__device__ __forceinline__ uint32_t packh2(float lo, float hi) {
    __half2 h = __floats2half2_rn(lo, hi);   // .x = lo (low 16 bits)
    return *reinterpret_cast<uint32_t*>(&h);
}
__device__ __forceinline__ uint32_t h2u(__half2 h) {
    return *reinterpret_cast<uint32_t*>(&h);
}

// ---------------- fp32 -> fp16 conversion (vectorized) ----------------
__global__ void cvt_f2h(const float* __restrict__ s, __half* __restrict__ d,
                        int n4) {
    int i = blockIdx.x * blockDim.x + threadIdx.x;
    if (i < n4) {
        float4 v = reinterpret_cast<const float4*>(s)[i];
        uint2 o;
        o.x = packh2(v.x, v.y);
        o.y = packh2(v.z, v.w);
        reinterpret_cast<uint2*>(d)[i] = o;
    }
}

// ==================== pipelined fp16 mma GEMM (fp32 accum) ====================
// C = A(M,K) @ W(K,N) (+bias). 256 thr = 8 warps (4m x 2n), BM=128 BN=64 BK=32.
// W is PRE-CONVERTED fp16 (row-major K x N). A either fp32 (+optional ids
// gather) or fp16. smem packed half2 (2 k per u32).
// As [2][128][20] u32, Ws [2][16][72] u32 — conflict-free fragment walks.
struct GemmArgs {
    const __half* A;
    const __half* W;
    const float* bias;
    float* C;
};

struct SrcA {
    const float* A;
    const int* ids;   // null -> direct rows
    int lda;
};

template <bool AHALF, bool ADDBIAS>
__device__ __forceinline__ void gemm_core(const void* __restrict__ Av,
                                          const int* __restrict__ ids,
                                          int lda, int kaoff,
                                          const __half* __restrict__ W,
                                          const float* __restrict__ bias,
                                          float* __restrict__ C,
                                          int N, int kbegW, int kT) {
    __shared__ uint32_t As[2][128][20];   // 20480 B
    __shared__ uint32_t Ws[2][16][72];    //  9216 B  (29696 total, static)

    const int tid = threadIdx.x;
    const int lane = tid & 31;
    const int wid = tid >> 5;
    const int gid = lane >> 2;
    const int tig = lane & 3;
    const int warp_m = (wid & 3) * 32;
    const int warp_n = (wid >> 2) * 32;

    const int bm = blockIdx.y * 128;
    const int bn = blockIdx.x * 64;

    // A staging: rows sa_r (+32r), k cols sa_c..sa_c+3 -> 2 packed u32
    const int sa_r = tid >> 3;           // 0..31
    const int sa_c = (tid & 7) * 4;      // 0..28
    const int sa_p = sa_c >> 1;          // pair col 0..14
    // W staging: k-pair row pk (covers k=2pk,2pk+1), n cols wc..wc+3
    const int pk = tid >> 4;             // 0..15
    const int wc = (tid & 15) * 4;       // 0..60
    const int gnw = bn + wc;
    const bool wok = (gnw < N);

    // per-stage A row pointers (gather if ids != null)
    const float* ArowF[4];
    const __half* ArowH[4];
#pragma unroll
    for (int r = 0; r < 4; r++) {
        int row = bm + sa_r + 32 * r;
        if (AHALF) {
            ArowH[r] = (const __half*)Av + (size_t)row * lda + kaoff + sa_c;
        } else {
            size_t src = ids ? (size_t)ids[row] : (size_t)row;
            ArowF[r] = (const float*)Av + src * (size_t)lda + kaoff + sa_c;
        }
    }

    const __half* Wp0 = W + (size_t)(kbegW + 2 * pk) * N + gnw;
    const __half* Wp1 = W + (size_t)(kbegW + 2 * pk + 1) * N + gnw;

    float acc[2][4][4];
#pragma unroll
    for (int mi = 0; mi < 2; mi++)
#pragma unroll
        for (int ni = 0; ni < 4; ni++)
#pragma unroll
            for (int r = 0; r < 4; r++) acc[mi][ni][r] = 0.f;

    float4 avf[4];
    uint2 avh[4];
    uint2 w0, w1;

    auto LDG = [&](int t) {
#pragma unroll
        for (int r = 0; r < 4; r++) {
            if (AHALF)
                avh[r] = *reinterpret_cast<const uint2*>(ArowH[r] + t * 32);
            else
                avf[r] = *reinterpret_cast<const float4*>(ArowF[r] + t * 32);
        }
        if (wok) {
            w0 = *reinterpret_cast<const uint2*>(Wp0 + (size_t)(t * 32) * N);
            w1 = *reinterpret_cast<const uint2*>(Wp1 + (size_t)(t * 32) * N);
        } else {
            w0 = make_uint2(0u, 0u);
            w1 = w0;
        }
    };

    auto STS = [&](int p) {
#pragma unroll
        for (int r = 0; r < 4; r++) {
            int m = sa_r + 32 * r;
            uint2 t2;
            if (AHALF) {
                t2 = avh[r];
            } else {
                t2.x = packh2(avf[r].x, avf[r].y);
                t2.y = packh2(avf[r].z, avf[r].w);
            }
            *reinterpret_cast<uint2*>(&As[p][m][sa_p]) = t2;
        }
        __half2 a0 = ((__half2*)&w0)[0], a1 = ((__half2*)&w0)[1];
        __half2 b0 = ((__half2*)&w1)[0], b1 = ((__half2*)&w1)[1];
        uint4 t4;
        t4.x = h2u(__lows2half2(a0, b0));
        t4.y = h2u(__highs2half2(a0, b0));
        t4.z = h2u(__lows2half2(a1, b1));
        t4.w = h2u(__highs2half2(a1, b1));
        *reinterpret_cast<uint4*>(&Ws[p][pk][wc]) = t4;
    };

    LDG(0);
    STS(0);
    __syncthreads();

    int p = 0;
    for (int t = 0; t < kT; t++) {
        if (t + 1 < kT) LDG(t + 1);

#pragma unroll
        for (int ks = 0; ks < 2; ks++) {       // two k=16 steps per 32-k tile
            const int kp = ks * 8;             // k-pair offset
            uint32_t af[2][4];
#pragma unroll
            for (int mi = 0; mi < 2; mi++) {
                int ar = warp_m + mi * 16 + gid;
                af[mi][0] = As[p][ar][kp + tig];
                af[mi][1] = As[p][ar + 8][kp + tig];
                af[mi][2] = As[p][ar][kp + tig + 4];
                af[mi][3] = As[p][ar + 8][kp + tig + 4];
            }
            uint32_t bf[4][2];
#pragma unroll
            for (int ni = 0; ni < 4; ni++) {
                int bc = warp_n + ni * 8 + gid;
                bf[ni][0] = Ws[p][kp + tig][bc];
                bf[ni][1] = Ws[p][kp + tig + 4][bc];
            }
#pragma unroll
            for (int mi = 0; mi < 2; mi++)
#pragma unroll
                for (int ni = 0; ni < 4; ni++) {
                    asm volatile(
                        "mma.sync.aligned.m16n8k16.row.col.f32.f16.f16.f32 "
                        "{%0,%1,%2,%3}, {%4,%5,%6,%7}, {%8,%9}, {%0,%1,%2,%3};\n"
                        : "+f"(acc[mi][ni][0]), "+f"(acc[mi][ni][1]),
                          "+f"(acc[mi][ni][2]), "+f"(acc[mi][ni][3])
                        : "r"(af[mi][0]), "r"(af[mi][1]),
                          "r"(af[mi][2]), "r"(af[mi][3]),
                          "r"(bf[ni][0]), "r"(bf[ni][1]));
                }
        }

        if (t + 1 < kT) STS(p ^ 1);
        __syncthreads();
        p ^= 1;
    }

    // epilogue
#pragma unroll
    for (int mi = 0; mi < 2; mi++) {
        int r0 = bm + warp_m + mi * 16 + gid;
#pragma unroll
        for (int ni = 0; ni < 4; ni++) {
            int c0 = bn + warp_n + ni * 8 + 2 * tig;
            if (c0 < N) {
                float v0 = acc[mi][ni][0], v1 = acc[mi][ni][1];
                float v2 = acc[mi][ni][2], v3 = acc[mi][ni][3];
                if (ADDBIAS) {
                    float bz0 = bias[c0];
                    float bz1 = (c0 + 1 < N) ? bias[c0 + 1] : 0.f;
                    v0 += bz0; v1 += bz1; v2 += bz0; v3 += bz1;
                }
                C[(size_t)r0 * N + c0] = v0;
                C[(size_t)(r0 + 8) * N + c0] = v2;
                if (c0 + 1 < N) {
                    C[(size_t)r0 * N + c0 + 1] = v1;
                    C[(size_t)(r0 + 8) * N + c0 + 1] = v3;
                }
            }
        }
    }
}

// split-K, fp32-A (optional gather) + fp16-W. z < zsplit reads s0 (chunk z),
// else s1 (chunk z-zsplit). Raw partials at Cb + z*M*N, no bias.
__global__ void __launch_bounds__(256)
gemm_h16_split(SrcA s0, SrcA s1, int zsplit, const __half* __restrict__ W,
               float* __restrict__ Cb, int M, int N, int kLen) {
    const int z = blockIdx.z;
    const SrcA s = (z < zsplit) ? s0 : s1;
    const int kaoff = ((z < zsplit) ? z : (z - zsplit)) * kLen;
    gemm_core<false, false>(s.A, s.ids, s.lda, kaoff, W, nullptr,
                            Cb + (size_t)z * M * N, N, z * kLen, kLen / 32);
}

// plain (full K, bias), fp16-A + fp16-W; dual via grid.z when dual != 0
__global__ void __launch_bounds__(256)
gemm_h16(GemmArgs g0, GemmArgs g1, int dual, int N, int K) {
    const GemmArgs ga = (dual && blockIdx.z == 1) ? g1 : g0;
    gemm_core<true, true>(ga.A, nullptr, K, 0, ga.W, ga.bias, ga.C, N, 0,
                          K / 32);
}

// ---------------- softmax (attn): sum ATTN_S K-partials + bias, then softmax ----------------
__global__ void softmax_attn_kernel(const float* __restrict__ attn_b,
                                    float* __restrict__ out) {
    int b = blockIdx.x;
    int t = threadIdx.x;
    float v = attn_b[t];
#pragma unroll
    for (int s = 0; s < ATTN_S; s++)
        v += g_part[(size_t)s * B_ * L_ + b * L_ + t];
    __shared__ float red[256];
    red[t] = v;
    __syncthreads();
    for (int s = 128; s; s >>= 1) {
        if (t < s) red[t] = fmaxf(red[t], red[t + s]);
        __syncthreads();
    }
    float m = red[0];
    __syncthreads();
    float e = expf(v - m);
    red[t] = e;
    __syncthreads();
    for (int s = 128; s; s >>= 1) {
        if (t < s) red[t] += red[t + s];
        __syncthreads();
    }
    out[b * L_ + t] = e / red[0];
}

// ---------------- reduce COMB_S K-partials + bias + relu -> g_x, g_x16 ----------------
__global__ void reduce_relu_kernel(const float* __restrict__ bias) {
    int i = blockIdx.x * blockDim.x + threadIdx.x;
    int j = i & (H_ - 1);
    float v = bias[j];
#pragma unroll
    for (int s = 0; s < COMB_S; s++)
        v += g_part[(size_t)s * B_ * H_ + i];
    v = fmaxf(v, 0.f);
    g_x[i] = v;
    g_x16[i] = __float2half_rn(v);
}

// ---------------- attn_applied -> g_app ----------------
__global__ void attn_apply_kernel(const float* __restrict__ attw,
                                  const float* __restrict__ enc) {
    int b = blockIdx.y;
    int hc = blockIdx.x;
    int t = threadIdx.x;
    __shared__ float w[L_];
    w[t] = attw[b * L_ + t];
    __syncthreads();
    int h = hc * 256 + t;
    const float* e = enc + (size_t)b * L_ * H_ + h;
    float acc = 0.f;
#pragma unroll 8
    for (int l = 0; l < L_; l++)
        acc += w[l] * e[(size_t)l * H_];
    g_app[(size_t)b * H_ + h] = acc;
}

// ---------------- GRU elementwise (writes fp32 out + fp16 mirror) ----------------
__global__ void gru_kernel(const float* __restrict__ h,
                           float* __restrict__ new_h) {
    int i = blockIdx.x * blockDim.x + threadIdx.x;
    int b = i >> 10;
    int j = i & (H_ - 1);
    const float* gib = g_gi + (size_t)b * H3_;
    const float* ghb = g_gh + (size_t)b * H3_;
    float r = 1.f / (1.f + expf(-(gib[j] + ghb[j])));
    float z = 1.f / (1.f + expf(-(gib[H_ + j] + ghb[H_ + j])));
    float n = tanhf(gib[2 * H_ + j] + r * ghb[2 * H_ + j]);
    float v = (1.f - z) * n + z * h[i];
    new_h[i] = v;
    g_nh16[i] = __float2half_rn(v);
}

// ---------------- log_softmax (online max+sum) ----------------
__global__ void logsoftmax_kernel(float* __restrict__ x) {
    int b = blockIdx.x;
    int t = threadIdx.x;
    float* row = x + (size_t)b * V_;
    __shared__ float redm[256];
    __shared__ float reds[256];
    float m = -1e30f, s = 0.f;
    for (int i = t; i < V_; i += 256) {
        float v = row[i];
        float mn = fmaxf(m, v);
        s = s * expf(m - mn) + expf(v - mn);
        m = mn;
    }
    redm[t] = m;
    reds[t] = s;
    __syncthreads();
    for (int st = 128; st; st >>= 1) {
        if (t < st) {
            float m2 = redm[t + st], s2 = reds[t + st];
            float mn = fmaxf(redm[t], m2);
            reds[t] = reds[t] * expf(redm[t] - mn) + s2 * expf(m2 - mn);
            redm[t] = mn;
        }
        __syncthreads();
    }
    float lse = redm[0] + logf(reds[0]);
    for (int i = t; i < V_; i += 256) row[i] -= lse;
}

// ---------------- launch ----------------
extern "C" void kernel_launch(void* const* d_in, const int* in_sizes, int n_in,
                              void* d_out, int out_size) {
    const int*   input_ids = (const int*)d_in[0];
    const float* hidden    = (const float*)d_in[1];
    const float* enc       = (const float*)d_in[2];
    const float* emb       = (const float*)d_in[3];
    const float* attn_w    = (const float*)d_in[4];
    const float* attn_b    = (const float*)d_in[5];
    const float* comb_w    = (const float*)d_in[6];
    const float* comb_b    = (const float*)d_in[7];
    const float* w_ih      = (const float*)d_in[8];
    const float* w_hh      = (const float*)d_in[9];
    const float* b_ih      = (const float*)d_in[10];
    const float* b_hh      = (const float*)d_in[11];
    const float* out_w     = (const float*)d_in[12];
    const float* out_b     = (const float*)d_in[13];

    float* out       = (float*)d_out;
    float* new_h_out = out + (size_t)B_ * V_;
    float* attw_out  = new_h_out + (size_t)B_ * H_;

    float *p_app, *p_x, *p_gi, *p_gh, *p_part;
    cudaGetSymbolAddress((void**)&p_app,  g_app);
    cudaGetSymbolAddress((void**)&p_x,    g_x);
    cudaGetSymbolAddress((void**)&p_gi,   g_gi);
    cudaGetSymbolAddress((void**)&p_gh,   g_gh);
    cudaGetSymbolAddress((void**)&p_part, g_part);

    __half *h_attn, *h_comb, *h_ih, *h_hh, *h_out, *h_hid, *h_x, *h_nh;
    cudaGetSymbolAddress((void**)&h_attn, g_w_attn16);
    cudaGetSymbolAddress((void**)&h_comb, g_w_comb16);
    cudaGetSymbolAddress((void**)&h_ih,   g_w_ih16);
    cudaGetSymbolAddress((void**)&h_hh,   g_w_hh16);
    cudaGetSymbolAddress((void**)&h_out,  g_w_out16);
    cudaGetSymbolAddress((void**)&h_hid,  g_hid16);
    cudaGetSymbolAddress((void**)&h_x,    g_x16);
    cudaGetSymbolAddress((void**)&h_nh,   g_nh16);

    GemmArgs none = {nullptr, nullptr, nullptr, nullptr};

    SrcA src_emb  = {emb,    input_ids, H_};   // gathered rows
    SrcA src_hid  = {hidden, nullptr,   H_};
    SrcA src_app  = {p_app,  nullptr,   H_};

    // 0. convert weights + hidden to fp16 (bit-identical to staging rounding)
    cvt_f2h<<<(H2_ * L_ / 4 + 255) / 256, 256>>>(attn_w, h_attn, H2_ * L_ / 4);
    cvt_f2h<<<(H2_ * H_ / 4 + 255) / 256, 256>>>(comb_w, h_comb, H2_ * H_ / 4);
    cvt_f2h<<<(H_ * H3_ / 4 + 255) / 256, 256>>>(w_ih, h_ih, H_ * H3_ / 4);
    cvt_f2h<<<(H_ * H3_ / 4 + 255) / 256, 256>>>(w_hh, h_hh, H_ * H3_ / 4);
    cvt_f2h<<<(H_ * V_ / 4 + 255) / 256, 256>>>(out_w, h_out, H_ * V_ / 4);
    cvt_f2h<<<(B_ * H_ / 4 + 255) / 256, 256>>>(hidden, h_hid, B_ * H_ / 4);

    // 1. attn logits = [emb[ids] | hidden] @ attn_w, split-K=16 -> partials
    {
        dim3 g(L_ / 64, B_ / 128, ATTN_S);
        gemm_h16_split<<<g, 256>>>(src_emb, src_hid, ATTN_S / 2, h_attn,
                                   p_part, B_, L_, H2_ / ATTN_S);
    }
    // 2. reduce partials + bias + softmax -> attw_out
    softmax_attn_kernel<<<B_, 256>>>(attn_b, attw_out);
    // 3. attn_applied -> g_app
    {
        dim3 g(H_ / 256, B_);
        attn_apply_kernel<<<g, 256>>>(attw_out, enc);
    }
    // 4. comb GEMM = [emb[ids] | attn_applied] @ comb_w, split-K=4 -> partials
    {
        dim3 g(H_ / 64, B_ / 128, COMB_S);
        gemm_h16_split<<<g, 256>>>(src_emb, src_app, COMB_S / 2, h_comb,
                                   p_part, B_, H_, H2_ / COMB_S);
    }
    // 5. x = relu(sum partials + bias), fp32 + fp16
    reduce_relu_kernel<<<(B_ * H_) / 256, 256>>>(comb_b);
    // 6. gi = x@w_ih+b_ih ; gh = hidden@w_hh+b_hh (dual via grid.z, all fp16)
    {
        dim3 g(H3_ / 64, B_ / 128, 2);
        GemmArgs a0 = {h_x,   h_ih, b_ih, p_gi};
        GemmArgs a1 = {h_hid, h_hh, b_hh, p_gh};
        gemm_h16<<<g, 256>>>(a0, a1, 1, H3_, H_);
    }
    // 7. GRU -> new_hidden (fp32 out + fp16 mirror)
    gru_kernel<<<(B_ * H_) / 256, 256>>>(hidden, new_h_out);
    // 8. out-proj (fp16 A + fp16 W)
    {
        dim3 g((V_ + 63) / 64, B_ / 128, 1);
        GemmArgs a0 = {h_nh, h_out, out_b, out};
        gemm_h16<<<g, 256>>>(a0, none, 0, V_, H_);
    }
    // 9. log_softmax (online)
    logsoftmax_kernel<<<B_, 256>>>(out);
}